// round 3
// baseline (speedup 1.0000x reference)
#include <cuda_runtime.h>
#include <cuda_bf16.h>
#include <math.h>

#define NPIX 262144
#define CDIM 434
#define KCLS 14
#define MPRO 10
#define KM   (KCLS*MPRO)      // 140
#define CP   144              // padded proto count for GEMM
#define KPAD 448              // padded C for GEMM k-loop (28*16)

// ---------------- scratch (device globals; no runtime alloc) ----------------
__device__ float g_c[(size_t)NPIX * CDIM];       // normalized features, 455MB
__device__ float g_protos[KM * CDIM];            // l2-normalized prototypes
__device__ float g_pT[KPAD * CP];                // transposed padded protos for GEMM
__device__ float g_e[(size_t)NPIX * MPRO];       // exp(sim[n, :, gt[n]]/eps)
__device__ float g_r[NPIX];                      // sinkhorn row scales
__device__ float g_colsum[3 * KM];               // per-iteration column sums
__device__ float g_f[KM * CDIM];                 // scattered feature sums
__device__ int   g_ncnt[KM];                     // per-bucket counts
__device__ int   g_Bcnt[KCLS];                   // class histogram
__device__ unsigned char g_corr[NPIX];           // correct-prediction flag

// ---------------- utils ----------------
__device__ __forceinline__ float warpSum(float v) {
    #pragma unroll
    for (int o = 16; o > 0; o >>= 1) v += __shfl_xor_sync(0xffffffffu, v, o);
    return v;
}

// 128-thread block sum, broadcast to all threads
__device__ __forceinline__ float blockSum128(float v, float* s4) {
    v = warpSum(v);
    if ((threadIdx.x & 31) == 0) s4[threadIdx.x >> 5] = v;
    __syncthreads();
    float tot = s4[0] + s4[1] + s4[2] + s4[3];
    __syncthreads();
    return tot;
}

// ---------------- K0a: zero scratch ----------------
__global__ void k_zero() {
    int stride = gridDim.x * blockDim.x;
    int t = blockIdx.x * blockDim.x + threadIdx.x;
    for (int i = t; i < KM * CDIM; i += stride) g_f[i] = 0.f;
    for (int i = t; i < KPAD * CP; i += stride) g_pT[i] = 0.f;
    for (int i = t; i < 3 * KM; i += stride) g_colsum[i] = 0.f;
    for (int i = t; i < KM; i += stride) g_ncnt[i] = 0;
    for (int i = t; i < KCLS; i += stride) g_Bcnt[i] = 0;
}

// ---------------- K0b: l2-normalize prototypes ----------------
__global__ void k_pnorm(const float* __restrict__ pin) {
    __shared__ float s4[4];
    int row = blockIdx.x, t = threadIdx.x;
    float v[4]; float ss = 0.f;
    #pragma unroll
    for (int i = 0; i < 4; i++) {
        int c = t + 128 * i;
        float x = (c < CDIM) ? pin[row * CDIM + c] : 0.f;
        v[i] = x; ss += x * x;
    }
    ss = blockSum128(ss, s4);
    float inv = 1.f / fmaxf(sqrtf(ss), 1e-12f);
    #pragma unroll
    for (int i = 0; i < 4; i++) {
        int c = t + 128 * i;
        if (c < CDIM) {
            float y = v[i] * inv;
            g_protos[row * CDIM + c] = y;
            g_pT[c * CP + row] = y;
        }
    }
}

// ---------------- K1: layernorm + l2norm of feat (warp per row) ----------------
__global__ void k_ln(const float* __restrict__ feat,
                     const float* __restrict__ gam,
                     const float* __restrict__ bet) {
    int w = blockIdx.x * 8 + (threadIdx.x >> 5);
    int lane = threadIdx.x & 31;
    size_t base = (size_t)w * CDIM;
    float v[14]; float s = 0.f;
    #pragma unroll
    for (int i = 0; i < 14; i++) {
        int c = lane + 32 * i;
        float x = (c < CDIM) ? feat[base + c] : 0.f;
        v[i] = x; s += x;
    }
    s = warpSum(s);
    float mu = s / (float)CDIM;
    float s2 = 0.f;
    #pragma unroll
    for (int i = 0; i < 14; i++) {
        int c = lane + 32 * i;
        if (c < CDIM) { float d = v[i] - mu; s2 += d * d; }
    }
    s2 = warpSum(s2);
    float inv = 1.f / sqrtf(s2 / (float)CDIM + 1e-5f);
    float sy = 0.f;
    #pragma unroll
    for (int i = 0; i < 14; i++) {
        int c = lane + 32 * i;
        if (c < CDIM) {
            float y = (v[i] - mu) * inv * gam[c] + bet[c];
            v[i] = y; sy += y * y;
        }
    }
    sy = warpSum(sy);
    float invn = 1.f / fmaxf(sqrtf(sy), 1e-12f);
    #pragma unroll
    for (int i = 0; i < 14; i++) {
        int c = lane + 32 * i;
        if (c < CDIM) g_c[base + c] = v[i] * invn;
    }
}

// ---------------- K2: GEMM logits = g_c @ g_pT ----------------
// Block: 128 rows x 144 cols (140 real). 256 thr, micro 8x9.
__global__ __launch_bounds__(256, 2) void k_gemm(float* __restrict__ o_log) {
    __shared__ float As[16][128];
    __shared__ float Bs[16][CP];
    int t = threadIdx.x;
    int rg = t & 15, cg = t >> 4;
    int r0 = blockIdx.x * 128;
    float acc[8][9];
    #pragma unroll
    for (int i = 0; i < 8; i++)
        #pragma unroll
        for (int j = 0; j < 9; j++) acc[i][j] = 0.f;

    for (int kc = 0; kc < KPAD; kc += 16) {
        #pragma unroll
        for (int i = 0; i < 8; i++) {
            int e = i * 256 + t; int kk = e & 15; int row = e >> 4;
            int col = kc + kk;
            As[kk][row] = (col < CDIM) ? g_c[(size_t)(r0 + row) * CDIM + col] : 0.f;
        }
        #pragma unroll
        for (int i = 0; i < 9; i++) {
            int e = i * 256 + t; int kk = e / CP; int col = e - kk * CP;
            Bs[kk][col] = g_pT[(kc + kk) * CP + col];
        }
        __syncthreads();
        #pragma unroll
        for (int k = 0; k < 16; k++) {
            float a[8], b[9];
            #pragma unroll
            for (int i = 0; i < 8; i++) a[i] = As[k][rg + 16 * i];
            #pragma unroll
            for (int j = 0; j < 9; j++) b[j] = Bs[k][cg * 9 + j];
            #pragma unroll
            for (int i = 0; i < 8; i++)
                #pragma unroll
                for (int j = 0; j < 9; j++) acc[i][j] += a[i] * b[j];
        }
        __syncthreads();
    }
    #pragma unroll
    for (int i = 0; i < 8; i++) {
        int row = r0 + rg + 16 * i;
        #pragma unroll
        for (int j = 0; j < 9; j++) {
            int col = cg * 9 + j;
            if (col < KM) o_log[(size_t)row * KM + col] = acc[i][j];
        }
    }
}

// ---------------- K3: epilogue: max over M, LN over K, pred/correct, E, hist ---
__global__ void k_epi(const float* __restrict__ logits,
                      const int* __restrict__ gts,
                      const float* __restrict__ mg,
                      const float* __restrict__ mb,
                      float* __restrict__ o_seg) {
    __shared__ float sh[64][141];
    __shared__ int hist[KCLS];
    int t = threadIdx.x;
    int p0 = blockIdx.x * 64;
    if (t < KCLS) hist[t] = 0;
    for (int i = t; i < 64 * KM; i += 256) {
        int p = i / KM, c = i - p * KM;
        sh[p][c] = logits[(size_t)(p0 + p) * KM + c];
    }
    __syncthreads();
    if (t < 64) {
        int n = p0 + t;
        float mx[KCLS]; float mean = 0.f;
        #pragma unroll
        for (int k = 0; k < KCLS; k++) {
            float m0 = sh[t][k * MPRO];
            #pragma unroll
            for (int m = 1; m < MPRO; m++) m0 = fmaxf(m0, sh[t][k * MPRO + m]);
            mx[k] = m0; mean += m0;
        }
        mean /= (float)KCLS;
        float var = 0.f;
        #pragma unroll
        for (int k = 0; k < KCLS; k++) { float d = mx[k] - mean; var += d * d; }
        var /= (float)KCLS;
        float inv = 1.f / sqrtf(var + 1e-5f);
        float best = -1e30f; int pred = 0;
        #pragma unroll
        for (int k = 0; k < KCLS; k++) {
            float v = (mx[k] - mean) * inv * mg[k] + mb[k];
            o_seg[(size_t)n * KCLS + k] = v;
            if (v > best) { best = v; pred = k; }
        }
        int gt = gts[n];
        g_corr[n] = (unsigned char)(pred == gt);
        #pragma unroll
        for (int m = 0; m < MPRO; m++)
            g_e[(size_t)n * MPRO + m] = expf(sh[t][gt * MPRO + m] / 0.05f);
        atomicAdd(&hist[gt], 1);
    }
    __syncthreads();
    if (t < KCLS) atomicAdd(&g_Bcnt[t], hist[t]);
}

// ---------------- K4: sinkhorn column sums (pass = 0,1,2) ----------------
__global__ void k_col(const int* __restrict__ gts, int pass) {
    __shared__ float part[KM];
    int t = threadIdx.x;
    if (t < KM) part[t] = 0.f;
    __syncthreads();
    int n = blockIdx.x * 256 + t;
    int k = gts[n];
    float rv = pass ? g_r[n] : 1.f;
    #pragma unroll
    for (int m = 0; m < MPRO; m++)
        atomicAdd(&part[k * MPRO + m], g_e[(size_t)n * MPRO + m] * rv);
    __syncthreads();
    if (t < KM) atomicAdd(&g_colsum[pass * KM + t], part[t]);
}

// ---------------- K5: sinkhorn row scales ----------------
__global__ void k_row(const int* __restrict__ gts, int pass) {
    int n = blockIdx.x * 256 + threadIdx.x;
    int k = gts[n];
    float rs = 0.f;
    #pragma unroll
    for (int m = 0; m < MPRO; m++) {
        float cs = g_colsum[pass * KM + k * MPRO + m];
        float c = 1.f / ((float)MPRO * fmaxf(cs, 1e-30f));
        rs += g_e[(size_t)n * MPRO + m] * c;
    }
    float B = (float)g_Bcnt[k];
    g_r[n] = 1.f / (fmaxf(B, 1.f) * fmaxf(rs, 1e-30f));
}

// ---------------- K6: argmax -> target, scatter f ----------------
__global__ void k_final(const int* __restrict__ gts, float* __restrict__ o_tgt) {
    int t = blockIdx.x * 256 + threadIdx.x;
    int lane = threadIdx.x & 31;
    int n = t;
    int k = gts[n];
    float best = -1e30f; int idx = 0;
    #pragma unroll
    for (int m = 0; m < MPRO; m++) {
        float cs = g_colsum[2 * KM + k * MPRO + m];
        float val = g_e[(size_t)n * MPRO + m] / fmaxf(cs, 1e-30f);
        if (val > best) { best = val; idx = m; }
    }
    o_tgt[n] = (float)(k * MPRO + idx);
    int bucket = k * MPRO + idx;
    int corr = (int)g_corr[n];
    unsigned mask = __ballot_sync(0xffffffffu, corr != 0);
    while (mask) {
        int src = __ffs(mask) - 1;
        mask &= mask - 1;
        int bn = __shfl_sync(0xffffffffu, n, src);
        int bb = __shfl_sync(0xffffffffu, bucket, src);
        const float* crow = g_c + (size_t)bn * CDIM;
        for (int c = lane; c < CDIM; c += 32)
            atomicAdd(&g_f[bb * CDIM + c], crow[c]);
        if (lane == src) atomicAdd(&g_ncnt[bb], 1);
    }
}

// ---------------- K7: prototype momentum update + final l2norm ----------------
__global__ void k_update(float* __restrict__ o_np) {
    __shared__ float s4[4];
    int row = blockIdx.x, t = threadIdx.x;
    float v[4]; float ss = 0.f;
    #pragma unroll
    for (int i = 0; i < 4; i++) {
        int c = t + 128 * i;
        float x = (c < CDIM) ? g_f[row * CDIM + c] : 0.f;
        v[i] = x; ss += x * x;
    }
    ss = blockSum128(ss, s4);
    float inv = 1.f / fmaxf(sqrtf(ss), 1e-12f);
    int cnt = g_ncnt[row];
    float ss2 = 0.f;
    #pragma unroll
    for (int i = 0; i < 4; i++) {
        int c = t + 128 * i;
        if (c < CDIM) {
            float p = g_protos[row * CDIM + c];
            float u = (cnt > 0) ? (0.999f * p + 0.001f * (v[i] * inv)) : p;
            v[i] = u; ss2 += u * u;
        } else v[i] = 0.f;
    }
    ss2 = blockSum128(ss2, s4);
    float inv2 = 1.f / fmaxf(sqrtf(ss2), 1e-12f);
    #pragma unroll
    for (int i = 0; i < 4; i++) {
        int c = t + 128 * i;
        if (c < CDIM) o_np[row * CDIM + c] = v[i] * inv2;
    }
}

// ---------------- launch ----------------
extern "C" void kernel_launch(void* const* d_in, const int* in_sizes, int n_in,
                              void* d_out, int out_size) {
    const float* feat = (const float*)d_in[0];
    const float* protos = (const float*)d_in[1];
    const float* fg = (const float*)d_in[2];
    const float* fb = (const float*)d_in[3];
    const float* mg = (const float*)d_in[4];
    const float* mb = (const float*)d_in[5];
    const int* gts = (const int*)d_in[6];

    float* out = (float*)d_out;
    float* o_seg = out;                                     // [N, 14]
    float* o_log = out + (size_t)NPIX * KCLS;               // [N, 140]
    float* o_tgt = out + (size_t)NPIX * (KCLS + KM);        // [N]
    float* o_np  = out + (size_t)NPIX * (KCLS + KM + 1);    // [140, 434]

    k_zero<<<256, 256>>>();
    k_pnorm<<<KM, 128>>>(protos);
    k_ln<<<NPIX / 8, 256>>>(feat, fg, fb);
    k_gemm<<<NPIX / 128, 256>>>(o_log);
    k_epi<<<NPIX / 64, 256>>>(o_log, gts, mg, mb, o_seg);
    k_col<<<NPIX / 256, 256>>>(gts, 0);
    k_row<<<NPIX / 256, 256>>>(gts, 0);
    k_col<<<NPIX / 256, 256>>>(gts, 1);
    k_row<<<NPIX / 256, 256>>>(gts, 1);
    k_col<<<NPIX / 256, 256>>>(gts, 2);
    k_final<<<NPIX / 256, 256>>>(gts, o_tgt);
    k_update<<<KM, 128>>>(o_np);
}

// round 7
// speedup vs baseline: 2.2107x; 2.2107x over previous
#include <cuda_runtime.h>
#include <cuda_bf16.h>
#include <math.h>
#include <stdint.h>

#define NPIX 262144
#define CDIM 434
#define CSTRIDE 448           // padded K (14 chunks of 32)
#define KCLS 14
#define MPRO 10
#define KM   140
#define NB   144              // padded proto count
#define NCHUNK 14

// ---------------- scratch (device globals) ----------------
__device__ __align__(128) __nv_bfloat16 g_chi[(size_t)NPIX * CSTRIDE];
__device__ __align__(128) __nv_bfloat16 g_clo[(size_t)NPIX * CSTRIDE];
__device__ __align__(128) __nv_bfloat16 g_bhi[NB * CSTRIDE];
__device__ __align__(128) __nv_bfloat16 g_blo[NB * CSTRIDE];
__device__ float g_protos[KM * CDIM];
__device__ float g_e[(size_t)NPIX * MPRO];
__device__ float g_r[NPIX];
__device__ float g_colsum[3 * KM];
__device__ float g_f[KM * CDIM];
__device__ int   g_ncnt[KM];
__device__ int   g_Bcnt[KCLS];
__device__ unsigned char g_corr[NPIX];

// ---------------- helpers ----------------
__device__ __forceinline__ uint32_t smem_u32(const void* p) {
    uint32_t a;
    asm("{ .reg .u64 t; cvta.to.shared.u64 t, %1; cvt.u32.u64 %0, t; }" : "=r"(a) : "l"(p));
    return a;
}
__device__ __forceinline__ void cp16(uint32_t dst, const void* src) {
    asm volatile("cp.async.cg.shared.global [%0], [%1], 16;" :: "r"(dst), "l"(src));
}
#define CP_COMMIT() asm volatile("cp.async.commit_group;" ::: "memory")
#define CP_WAIT0()  asm volatile("cp.async.wait_group 0;" ::: "memory")
#define CP_WAIT1()  asm volatile("cp.async.wait_group 1;" ::: "memory")

__device__ __forceinline__ void ldx4(uint32_t* r, uint32_t a) {
    asm volatile("ldmatrix.sync.aligned.m8n8.x4.shared.b16 {%0,%1,%2,%3}, [%4];"
        : "=r"(r[0]), "=r"(r[1]), "=r"(r[2]), "=r"(r[3]) : "r"(a));
}
__device__ __forceinline__ void ldx2(uint32_t* r, uint32_t a) {
    asm volatile("ldmatrix.sync.aligned.m8n8.x2.shared.b16 {%0,%1}, [%2];"
        : "=r"(r[0]), "=r"(r[1]) : "r"(a));
}
__device__ __forceinline__ void mma_bf16(float* c, const uint32_t* a, const uint32_t* b) {
    asm volatile("mma.sync.aligned.m16n8k16.row.col.f32.bf16.bf16.f32 "
        "{%0,%1,%2,%3}, {%4,%5,%6,%7}, {%8,%9}, {%0,%1,%2,%3};"
        : "+f"(c[0]), "+f"(c[1]), "+f"(c[2]), "+f"(c[3])
        : "r"(a[0]), "r"(a[1]), "r"(a[2]), "r"(a[3]), "r"(b[0]), "r"(b[1]));
}

__device__ __forceinline__ float warpSum(float v) {
    #pragma unroll
    for (int o = 16; o > 0; o >>= 1) v += __shfl_xor_sync(0xffffffffu, v, o);
    return v;
}
__device__ __forceinline__ float blockSum128(float v, float* s4) {
    v = warpSum(v);
    if ((threadIdx.x & 31) == 0) s4[threadIdx.x >> 5] = v;
    __syncthreads();
    float tot = s4[0] + s4[1] + s4[2] + s4[3];
    __syncthreads();
    return tot;
}

// ---------------- K0a: zero scratch ----------------
__global__ void k_zero() {
    int stride = gridDim.x * blockDim.x;
    int t = blockIdx.x * blockDim.x + threadIdx.x;
    for (int i = t; i < KM * CDIM; i += stride) g_f[i] = 0.f;
    for (int i = t; i < NB * CSTRIDE; i += stride) {
        g_bhi[i] = __float2bfloat16(0.f);
        g_blo[i] = __float2bfloat16(0.f);
    }
    for (int i = t; i < 3 * KM; i += stride) g_colsum[i] = 0.f;
    for (int i = t; i < KM; i += stride) g_ncnt[i] = 0;
    for (int i = t; i < KCLS; i += stride) g_Bcnt[i] = 0;
}

// ---------------- K0b: l2-normalize prototypes + bf16 split ----------------
__global__ void k_pnorm(const float* __restrict__ pin) {
    __shared__ float s4[4];
    int row = blockIdx.x, t = threadIdx.x;
    float v[4]; float ss = 0.f;
    #pragma unroll
    for (int i = 0; i < 4; i++) {
        int c = t + 128 * i;
        float x = (c < CDIM) ? pin[row * CDIM + c] : 0.f;
        v[i] = x; ss += x * x;
    }
    ss = blockSum128(ss, s4);
    float inv = 1.f / fmaxf(sqrtf(ss), 1e-12f);
    #pragma unroll
    for (int i = 0; i < 4; i++) {
        int c = t + 128 * i;
        if (c < CDIM) {
            float y = v[i] * inv;
            g_protos[row * CDIM + c] = y;
            __nv_bfloat16 h = __float2bfloat16(y);
            g_bhi[row * CSTRIDE + c] = h;
            g_blo[row * CSTRIDE + c] = __float2bfloat16(y - __bfloat162float(h));
        }
    }
}

// ---------------- K1: layernorm + l2norm of feat; write bf16 hi/lo ----------
__global__ void k_ln(const float* __restrict__ feat,
                     const float* __restrict__ gam,
                     const float* __restrict__ bet) {
    int w = blockIdx.x * 8 + (threadIdx.x >> 5);
    int lane = threadIdx.x & 31;
    size_t ibase = (size_t)w * CDIM;
    size_t obase = (size_t)w * CSTRIDE;
    float v[14]; float s = 0.f;
    #pragma unroll
    for (int i = 0; i < 14; i++) {
        int c = lane + 32 * i;
        float x = (c < CDIM) ? feat[ibase + c] : 0.f;
        v[i] = x; s += x;
    }
    s = warpSum(s);
    float mu = s / (float)CDIM;
    float s2 = 0.f;
    #pragma unroll
    for (int i = 0; i < 14; i++) {
        int c = lane + 32 * i;
        if (c < CDIM) { float d = v[i] - mu; s2 += d * d; }
    }
    s2 = warpSum(s2);
    float inv = 1.f / sqrtf(s2 / (float)CDIM + 1e-5f);
    float sy = 0.f;
    #pragma unroll
    for (int i = 0; i < 14; i++) {
        int c = lane + 32 * i;
        if (c < CDIM) {
            float y = (v[i] - mu) * inv * gam[c] + bet[c];
            v[i] = y; sy += y * y;
        } else v[i] = 0.f;
    }
    sy = warpSum(sy);
    float invn = 1.f / fmaxf(sqrtf(sy), 1e-12f);
    #pragma unroll
    for (int i = 0; i < 14; i++) {
        int c = lane + 32 * i;
        float y = v[i] * invn;
        __nv_bfloat16 h = __float2bfloat16(y);
        g_chi[obase + c] = h;
        g_clo[obase + c] = __float2bfloat16(y - __bfloat162float(h));
    }
}

// ---------------- K2: GEMM via mma.sync bf16 (3-pass split) -----------------
// Block: 128 M x 144 N, 8 warps (4x2), warp tile 32x72. BK=32, 2-stage cp.async.
// smem rows: 32 bf16 data padded to 40 (80B stride) -> conflict-free ldmatrix.
#define A_HI 0
#define A_LO 10240
#define B_HI 20480
#define B_LO 32000
#define SSTAGE 43520
#define GEMM_SMEM (2 * SSTAGE)

__device__ __forceinline__ void issue_loads(uint32_t sb, int s, int c, int r0, int tid) {
    uint32_t base = sb + s * SSTAGE;
    // A: 128 rows x 64B, hi+lo = 1024 x 16B
    #pragma unroll
    for (int q = 0; q < 4; q++) {
        int i = tid + 256 * q;
        int arr = i >> 9;
        int rem = i & 511;
        int r = rem >> 2, j = rem & 3;
        uint32_t dst = base + (arr ? A_LO : A_HI) + r * 80 + j * 16;
        const char* srcb = arr ? (const char*)g_clo : (const char*)g_chi;
        cp16(dst, srcb + ((size_t)(r0 + r) * CSTRIDE) * 2 + c * 64 + j * 16);
    }
    // B: 144 rows x 64B, hi+lo = 1152 x 16B
    for (int i = tid; i < 1152; i += 256) {
        int arr = (i >= 576);
        int rem = arr ? i - 576 : i;
        int r = rem >> 2, j = rem & 3;
        uint32_t dst = base + (arr ? B_LO : B_HI) + r * 80 + j * 16;
        const char* srcb = arr ? (const char*)g_blo : (const char*)g_bhi;
        cp16(dst, srcb + ((size_t)r * CSTRIDE) * 2 + c * 64 + j * 16);
    }
    CP_COMMIT();
}

__global__ __launch_bounds__(256, 1) void k_gemm_mma(float* __restrict__ o_log) {
    extern __shared__ char smem[];
    uint32_t sb = smem_u32(smem);
    int tid = threadIdx.x, lane = tid & 31, wid = tid >> 5;
    int warp_m = wid & 3, warp_n = wid >> 2;
    int r0 = blockIdx.x * 128;

    float C[2][9][4];
    #pragma unroll
    for (int t = 0; t < 2; t++)
        #pragma unroll
        for (int j = 0; j < 9; j++)
            #pragma unroll
            for (int q = 0; q < 4; q++) C[t][j][q] = 0.f;

    // ldmatrix lane address offsets
    uint32_t aoff  = (uint32_t)((warp_m * 32 + (lane & 15)) * 80 + (lane >> 4) * 16);
    uint32_t boff4 = (uint32_t)((warp_n * 72 + (lane & 7)) * 80 + ((lane >> 3) & 1) * 16 + (lane >> 4) * 640);
    uint32_t boff2 = (uint32_t)((warp_n * 72 + 64 + (lane & 7)) * 80 + ((lane >> 3) & 1) * 16);

    issue_loads(sb, 0, 0, r0, tid);
    issue_loads(sb, 1, 1, r0, tid);

    for (int c = 0; c < NCHUNK; c++) {
        int s = c & 1;
        if (c == NCHUNK - 1) { CP_WAIT0(); } else { CP_WAIT1(); }
        __syncthreads();
        uint32_t base = sb + s * SSTAGE;
        #pragma unroll
        for (int ks = 0; ks < 2; ks++) {
            uint32_t kb = ks * 32;
            uint32_t ah[2][4], al[2][4];
            ldx4(ah[0], base + A_HI + aoff + kb);
            ldx4(ah[1], base + A_HI + aoff + 1280 + kb);
            ldx4(al[0], base + A_LO + aoff + kb);
            ldx4(al[1], base + A_LO + aoff + 1280 + kb);
            uint32_t bh[9][2], bl[9][2];
            #pragma unroll
            for (int j = 0; j < 8; j += 2) {
                uint32_t q[4];
                ldx4(q, base + B_HI + boff4 + j * 640 + kb);
                bh[j][0] = q[0]; bh[j][1] = q[1]; bh[j + 1][0] = q[2]; bh[j + 1][1] = q[3];
                ldx4(q, base + B_LO + boff4 + j * 640 + kb);
                bl[j][0] = q[0]; bl[j][1] = q[1]; bl[j + 1][0] = q[2]; bl[j + 1][1] = q[3];
            }
            ldx2(bh[8], base + B_HI + boff2 + kb);
            ldx2(bl[8], base + B_LO + boff2 + kb);
            #pragma unroll
            for (int t = 0; t < 2; t++)
                #pragma unroll
                for (int j = 0; j < 9; j++) {
                    mma_bf16(C[t][j], ah[t], bh[j]);
                    mma_bf16(C[t][j], ah[t], bl[j]);
                    mma_bf16(C[t][j], al[t], bh[j]);
                }
        }
        __syncthreads();
        if (c + 2 < NCHUNK) issue_loads(sb, s, c + 2, r0, tid);
    }

    // epilogue: direct global stores (pairs), drop padded cols >= 140
    #pragma unroll
    for (int t = 0; t < 2; t++) {
        int rb = r0 + warp_m * 32 + t * 16 + (lane >> 2);
        #pragma unroll
        for (int j = 0; j < 9; j++) {
            int cb = warp_n * 72 + j * 8 + 2 * (lane & 3);
            if (cb < KM) {
                *(float2*)(o_log + (size_t)rb * KM + cb) = make_float2(C[t][j][0], C[t][j][1]);
                *(float2*)(o_log + (size_t)(rb + 8) * KM + cb) = make_float2(C[t][j][2], C[t][j][3]);
            }
        }
    }
}

// ---------------- K3: epilogue: max/LN/pred, E, hist ----------------
__global__ void k_epi(const float* __restrict__ logits,
                      const int* __restrict__ gts,
                      const float* __restrict__ mg,
                      const float* __restrict__ mb,
                      float* __restrict__ o_seg) {
    __shared__ float sh[64][141];
    __shared__ int hist[KCLS];
    int t = threadIdx.x;
    int p0 = blockIdx.x * 64;
    if (t < KCLS) hist[t] = 0;
    for (int i = t; i < 64 * KM; i += 256) {
        int p = i / KM, c = i - p * KM;
        sh[p][c] = logits[(size_t)(p0 + p) * KM + c];
    }
    __syncthreads();
    if (t < 64) {
        int n = p0 + t;
        float mx[KCLS]; float mean = 0.f;
        #pragma unroll
        for (int k = 0; k < KCLS; k++) {
            float m0 = sh[t][k * MPRO];
            #pragma unroll
            for (int m = 1; m < MPRO; m++) m0 = fmaxf(m0, sh[t][k * MPRO + m]);
            mx[k] = m0; mean += m0;
        }
        mean /= (float)KCLS;
        float var = 0.f;
        #pragma unroll
        for (int k = 0; k < KCLS; k++) { float d = mx[k] - mean; var += d * d; }
        var /= (float)KCLS;
        float inv = 1.f / sqrtf(var + 1e-5f);
        float best = -1e30f; int pred = 0;
        #pragma unroll
        for (int k = 0; k < KCLS; k++) {
            float v = (mx[k] - mean) * inv * mg[k] + mb[k];
            o_seg[(size_t)n * KCLS + k] = v;
            if (v > best) { best = v; pred = k; }
        }
        int gt = gts[n];
        g_corr[n] = (unsigned char)(pred == gt);
        #pragma unroll
        for (int m = 0; m < MPRO; m++)
            g_e[(size_t)n * MPRO + m] = expf(sh[t][gt * MPRO + m] / 0.05f);
        atomicAdd(&hist[gt], 1);
    }
    __syncthreads();
    if (t < KCLS) atomicAdd(&g_Bcnt[t], hist[t]);
}

// ---------------- K4: sinkhorn column sums ----------------
__global__ void k_col(const int* __restrict__ gts, int pass) {
    __shared__ float part[KM];
    int t = threadIdx.x;
    if (t < KM) part[t] = 0.f;
    __syncthreads();
    int n = blockIdx.x * 256 + t;
    int k = gts[n];
    float rv = pass ? g_r[n] : 1.f;
    #pragma unroll
    for (int m = 0; m < MPRO; m++)
        atomicAdd(&part[k * MPRO + m], g_e[(size_t)n * MPRO + m] * rv);
    __syncthreads();
    if (t < KM) atomicAdd(&g_colsum[pass * KM + t], part[t]);
}

// ---------------- K5: sinkhorn row scales ----------------
__global__ void k_row(const int* __restrict__ gts, int pass) {
    int n = blockIdx.x * 256 + threadIdx.x;
    int k = gts[n];
    float rs = 0.f;
    #pragma unroll
    for (int m = 0; m < MPRO; m++) {
        float cs = g_colsum[pass * KM + k * MPRO + m];
        float c = 1.f / ((float)MPRO * fmaxf(cs, 1e-30f));
        rs += g_e[(size_t)n * MPRO + m] * c;
    }
    float B = (float)g_Bcnt[k];
    g_r[n] = 1.f / (fmaxf(B, 1.f) * fmaxf(rs, 1e-30f));
}

// ---------------- K6: argmax -> target, scatter f ----------------
__global__ void k_final(const int* __restrict__ gts, float* __restrict__ o_tgt) {
    int n = blockIdx.x * 256 + threadIdx.x;
    int lane = threadIdx.x & 31;
    int k = gts[n];
    float best = -1e30f; int idx = 0;
    #pragma unroll
    for (int m = 0; m < MPRO; m++) {
        float cs = g_colsum[2 * KM + k * MPRO + m];
        float val = g_e[(size_t)n * MPRO + m] / fmaxf(cs, 1e-30f);
        if (val > best) { best = val; idx = m; }
    }
    o_tgt[n] = (float)(k * MPRO + idx);
    int bucket = k * MPRO + idx;
    int corr = (int)g_corr[n];
    unsigned mask = __ballot_sync(0xffffffffu, corr != 0);
    while (mask) {
        int src = __ffs(mask) - 1;
        mask &= mask - 1;
        int bn = __shfl_sync(0xffffffffu, n, src);
        int bb = __shfl_sync(0xffffffffu, bucket, src);
        const __nv_bfloat16* ch = g_chi + (size_t)bn * CSTRIDE;
        const __nv_bfloat16* cl = g_clo + (size_t)bn * CSTRIDE;
        for (int c = lane; c < CDIM; c += 32)
            atomicAdd(&g_f[bb * CDIM + c],
                      __bfloat162float(ch[c]) + __bfloat162float(cl[c]));
        if (lane == src) atomicAdd(&g_ncnt[bb], 1);
    }
}

// ---------------- K7: prototype momentum update + final l2norm --------------
__global__ void k_update(float* __restrict__ o_np) {
    __shared__ float s4[4];
    int row = blockIdx.x, t = threadIdx.x;
    float v[4]; float ss = 0.f;
    #pragma unroll
    for (int i = 0; i < 4; i++) {
        int c = t + 128 * i;
        float x = (c < CDIM) ? g_f[row * CDIM + c] : 0.f;
        v[i] = x; ss += x * x;
    }
    ss = blockSum128(ss, s4);
    float inv = 1.f / fmaxf(sqrtf(ss), 1e-12f);
    int cnt = g_ncnt[row];
    float ss2 = 0.f;
    #pragma unroll
    for (int i = 0; i < 4; i++) {
        int c = t + 128 * i;
        if (c < CDIM) {
            float p = g_protos[row * CDIM + c];
            float u = (cnt > 0) ? (0.999f * p + 0.001f * (v[i] * inv)) : p;
            v[i] = u; ss2 += u * u;
        } else v[i] = 0.f;
    }
    ss2 = blockSum128(ss2, s4);
    float inv2 = 1.f / fmaxf(sqrtf(ss2), 1e-12f);
    #pragma unroll
    for (int i = 0; i < 4; i++) {
        int c = t + 128 * i;
        if (c < CDIM) o_np[row * CDIM + c] = v[i] * inv2;
    }
}

// ---------------- launch ----------------
extern "C" void kernel_launch(void* const* d_in, const int* in_sizes, int n_in,
                              void* d_out, int out_size) {
    const float* feat = (const float*)d_in[0];
    const float* protos = (const float*)d_in[1];
    const float* fg = (const float*)d_in[2];
    const float* fb = (const float*)d_in[3];
    const float* mg = (const float*)d_in[4];
    const float* mb = (const float*)d_in[5];
    const int* gts = (const int*)d_in[6];

    float* out = (float*)d_out;
    float* o_seg = out;                                     // [N, 14]
    float* o_log = out + (size_t)NPIX * KCLS;               // [N, 140]
    float* o_tgt = out + (size_t)NPIX * (KCLS + KM);        // [N]
    float* o_np  = out + (size_t)NPIX * (KCLS + KM + 1);    // [140, 434]

    cudaFuncSetAttribute(k_gemm_mma, cudaFuncAttributeMaxDynamicSharedMemorySize, GEMM_SMEM);

    k_zero<<<256, 256>>>();
    k_pnorm<<<KM, 128>>>(protos);
    k_ln<<<NPIX / 8, 256>>>(feat, fg, fb);
    k_gemm_mma<<<NPIX / 128, 256, GEMM_SMEM>>>(o_log);
    k_epi<<<NPIX / 64, 256>>>(o_log, gts, mg, mb, o_seg);
    k_col<<<NPIX / 256, 256>>>(gts, 0);
    k_row<<<NPIX / 256, 256>>>(gts, 0);
    k_col<<<NPIX / 256, 256>>>(gts, 1);
    k_row<<<NPIX / 256, 256>>>(gts, 1);
    k_col<<<NPIX / 256, 256>>>(gts, 2);
    k_final<<<NPIX / 256, 256>>>(gts, o_tgt);
    k_update<<<KM, 128>>>(o_np);
}

// round 8
// speedup vs baseline: 2.5653x; 1.1604x over previous
#include <cuda_runtime.h>
#include <cuda_bf16.h>
#include <math.h>
#include <stdint.h>

#define NPIX 262144
#define CDIM 434
#define CSTRIDE 448           // padded K (14 chunks of 32)
#define KCLS 14
#define MPRO 10
#define KM   140
#define NB   144              // padded proto count
#define NCHUNK 14

// ---------------- scratch (device globals) ----------------
__device__ __align__(128) __nv_bfloat16 g_chi[(size_t)NPIX * CSTRIDE];
__device__ __align__(128) __nv_bfloat16 g_clo[(size_t)NPIX * CSTRIDE];
__device__ __align__(128) __nv_bfloat16 g_bhi[NB * CSTRIDE];
__device__ __align__(128) __nv_bfloat16 g_blo[NB * CSTRIDE];
__device__ float g_protos[KM * CDIM];
__device__ float g_e[(size_t)NPIX * MPRO];
__device__ float g_colsum[3 * KM];
__device__ float g_f[KM * CDIM];
__device__ int   g_ncnt[KM];
__device__ int   g_Bcnt[KCLS];
__device__ unsigned char g_corr[NPIX];

// ---------------- helpers ----------------
__device__ __forceinline__ uint32_t smem_u32(const void* p) {
    uint32_t a;
    asm("{ .reg .u64 t; cvta.to.shared.u64 t, %1; cvt.u32.u64 %0, t; }" : "=r"(a) : "l"(p));
    return a;
}
__device__ __forceinline__ void cp16(uint32_t dst, const void* src) {
    asm volatile("cp.async.cg.shared.global [%0], [%1], 16;" :: "r"(dst), "l"(src));
}
#define CP_COMMIT() asm volatile("cp.async.commit_group;" ::: "memory")
#define CP_WAIT0()  asm volatile("cp.async.wait_group 0;" ::: "memory")
#define CP_WAIT1()  asm volatile("cp.async.wait_group 1;" ::: "memory")

__device__ __forceinline__ void ldx4(uint32_t* r, uint32_t a) {
    asm volatile("ldmatrix.sync.aligned.m8n8.x4.shared.b16 {%0,%1,%2,%3}, [%4];"
        : "=r"(r[0]), "=r"(r[1]), "=r"(r[2]), "=r"(r[3]) : "r"(a));
}
__device__ __forceinline__ void ldx2(uint32_t* r, uint32_t a) {
    asm volatile("ldmatrix.sync.aligned.m8n8.x2.shared.b16 {%0,%1}, [%2];"
        : "=r"(r[0]), "=r"(r[1]) : "r"(a));
}
__device__ __forceinline__ void mma_bf16(float* c, const uint32_t* a, const uint32_t* b) {
    asm volatile("mma.sync.aligned.m16n8k16.row.col.f32.bf16.bf16.f32 "
        "{%0,%1,%2,%3}, {%4,%5,%6,%7}, {%8,%9}, {%0,%1,%2,%3};"
        : "+f"(c[0]), "+f"(c[1]), "+f"(c[2]), "+f"(c[3])
        : "r"(a[0]), "r"(a[1]), "r"(a[2]), "r"(a[3]), "r"(b[0]), "r"(b[1]));
}

__device__ __forceinline__ float warpSum(float v) {
    #pragma unroll
    for (int o = 16; o > 0; o >>= 1) v += __shfl_xor_sync(0xffffffffu, v, o);
    return v;
}
__device__ __forceinline__ float blockSum128(float v, float* s4) {
    v = warpSum(v);
    if ((threadIdx.x & 31) == 0) s4[threadIdx.x >> 5] = v;
    __syncthreads();
    float tot = s4[0] + s4[1] + s4[2] + s4[3];
    __syncthreads();
    return tot;
}

// ---------------- K0a: zero scratch ----------------
__global__ void k_zero() {
    int stride = gridDim.x * blockDim.x;
    int t = blockIdx.x * blockDim.x + threadIdx.x;
    for (int i = t; i < KM * CDIM; i += stride) g_f[i] = 0.f;
    for (int i = t; i < NB * CSTRIDE; i += stride) {
        g_bhi[i] = __float2bfloat16(0.f);
        g_blo[i] = __float2bfloat16(0.f);
    }
    for (int i = t; i < 3 * KM; i += stride) g_colsum[i] = 0.f;
    for (int i = t; i < KM; i += stride) g_ncnt[i] = 0;
    for (int i = t; i < KCLS; i += stride) g_Bcnt[i] = 0;
}

// ---------------- K0b: l2-normalize prototypes + bf16 split ----------------
__global__ void k_pnorm(const float* __restrict__ pin) {
    __shared__ float s4[4];
    int row = blockIdx.x, t = threadIdx.x;
    float v[4]; float ss = 0.f;
    #pragma unroll
    for (int i = 0; i < 4; i++) {
        int c = t + 128 * i;
        float x = (c < CDIM) ? pin[row * CDIM + c] : 0.f;
        v[i] = x; ss += x * x;
    }
    ss = blockSum128(ss, s4);
    float inv = 1.f / fmaxf(sqrtf(ss), 1e-12f);
    #pragma unroll
    for (int i = 0; i < 4; i++) {
        int c = t + 128 * i;
        if (c < CDIM) {
            float y = v[i] * inv;
            g_protos[row * CDIM + c] = y;
            __nv_bfloat16 h = __float2bfloat16(y);
            g_bhi[row * CSTRIDE + c] = h;
            g_blo[row * CSTRIDE + c] = __float2bfloat16(y - __bfloat162float(h));
        }
    }
}

// ---------------- K1: layernorm + l2norm of feat; write bf16 hi/lo ----------
__global__ void k_ln(const float* __restrict__ feat,
                     const float* __restrict__ gam,
                     const float* __restrict__ bet) {
    int w = blockIdx.x * 8 + (threadIdx.x >> 5);
    int lane = threadIdx.x & 31;
    size_t ibase = (size_t)w * CDIM;
    size_t obase = (size_t)w * CSTRIDE;
    float v[14]; float s = 0.f;
    #pragma unroll
    for (int i = 0; i < 14; i++) {
        int c = lane + 32 * i;
        float x = (c < CDIM) ? feat[ibase + c] : 0.f;
        v[i] = x; s += x;
    }
    s = warpSum(s);
    float mu = s / (float)CDIM;
    float s2 = 0.f;
    #pragma unroll
    for (int i = 0; i < 14; i++) {
        int c = lane + 32 * i;
        if (c < CDIM) { float d = v[i] - mu; s2 += d * d; }
    }
    s2 = warpSum(s2);
    float inv = 1.f / sqrtf(s2 / (float)CDIM + 1e-5f);
    float sy = 0.f;
    #pragma unroll
    for (int i = 0; i < 14; i++) {
        int c = lane + 32 * i;
        if (c < CDIM) {
            float y = (v[i] - mu) * inv * gam[c] + bet[c];
            v[i] = y; sy += y * y;
        } else v[i] = 0.f;
    }
    sy = warpSum(sy);
    float invn = 1.f / fmaxf(sqrtf(sy), 1e-12f);
    #pragma unroll
    for (int i = 0; i < 14; i++) {
        int c = lane + 32 * i;
        float y = v[i] * invn;
        __nv_bfloat16 h = __float2bfloat16(y);
        g_chi[obase + c] = h;
        g_clo[obase + c] = __float2bfloat16(y - __bfloat162float(h));
    }
}

// ---------------- K2: GEMM (mma.sync bf16, 3-pass) + fused epilogue ---------
// Block: 128 M x 144 N, 8 warps (4x2), warp tile 32x72. BK=32, 2-stage cp.async.
// smem rows: 32 bf16 padded to 40 (80B stride) -> conflict-free ldmatrix.
#define A_HI 0
#define A_LO 10240
#define B_HI 20480
#define B_LO 32000
#define SSTAGE 43520
#define CSTRIDE_EPI 145
#define OFF_PART 74240
#define OFF_HIST 74816
#define GEMM_SMEM 87040

__device__ __forceinline__ void issue_loads(uint32_t sb, int s, int c, int r0, int tid) {
    uint32_t base = sb + s * SSTAGE;
    // A: 128 rows x 64B, hi+lo = 1024 x 16B
    #pragma unroll
    for (int q = 0; q < 4; q++) {
        int i = tid + 256 * q;
        int arr = i >> 9;
        int rem = i & 511;
        int r = rem >> 2, j = rem & 3;
        uint32_t dst = base + (arr ? A_LO : A_HI) + r * 80 + j * 16;
        const char* srcb = arr ? (const char*)g_clo : (const char*)g_chi;
        cp16(dst, srcb + ((size_t)(r0 + r) * CSTRIDE) * 2 + c * 64 + j * 16);
    }
    // B: 144 rows x 64B, hi+lo = 1152 x 16B
    for (int i = tid; i < 1152; i += 256) {
        int arr = (i >= 576);
        int rem = arr ? i - 576 : i;
        int r = rem >> 2, j = rem & 3;
        uint32_t dst = base + (arr ? B_LO : B_HI) + r * 80 + j * 16;
        const char* srcb = arr ? (const char*)g_blo : (const char*)g_bhi;
        cp16(dst, srcb + ((size_t)r * CSTRIDE) * 2 + c * 64 + j * 16);
    }
    CP_COMMIT();
}

__global__ __launch_bounds__(256, 2) void k_gemm_mma(
        float* __restrict__ o_log,
        const int* __restrict__ gts,
        const float* __restrict__ mg,
        const float* __restrict__ mb,
        float* __restrict__ o_seg) {
    extern __shared__ char smem[];
    uint32_t sb = smem_u32(smem);
    int tid = threadIdx.x, lane = tid & 31, wid = tid >> 5;
    int warp_m = wid & 3, warp_n = wid >> 2;
    int r0 = blockIdx.x * 128;

    float C[2][9][4];
    #pragma unroll
    for (int t = 0; t < 2; t++)
        #pragma unroll
        for (int j = 0; j < 9; j++)
            #pragma unroll
            for (int q = 0; q < 4; q++) C[t][j][q] = 0.f;

    uint32_t aoff  = (uint32_t)((warp_m * 32 + (lane & 15)) * 80 + (lane >> 4) * 16);
    uint32_t boff4 = (uint32_t)((warp_n * 72 + (lane & 7)) * 80 + ((lane >> 3) & 1) * 16 + (lane >> 4) * 640);
    uint32_t boff2 = (uint32_t)((warp_n * 72 + 64 + (lane & 7)) * 80 + ((lane >> 3) & 1) * 16);

    issue_loads(sb, 0, 0, r0, tid);
    issue_loads(sb, 1, 1, r0, tid);

    for (int c = 0; c < NCHUNK; c++) {
        int s = c & 1;
        if (c == NCHUNK - 1) { CP_WAIT0(); } else { CP_WAIT1(); }
        __syncthreads();
        uint32_t base = sb + s * SSTAGE;
        #pragma unroll
        for (int ks = 0; ks < 2; ks++) {
            uint32_t kb = ks * 32;
            uint32_t ah[2][4], al[2][4];
            ldx4(ah[0], base + A_HI + aoff + kb);
            ldx4(ah[1], base + A_HI + aoff + 1280 + kb);
            ldx4(al[0], base + A_LO + aoff + kb);
            ldx4(al[1], base + A_LO + aoff + 1280 + kb);
            // process B in pairs of j: only 8 b-regs live at a time
            #pragma unroll
            for (int jp = 0; jp < 4; jp++) {
                uint32_t qh[4], ql[4];
                ldx4(qh, base + B_HI + boff4 + jp * 1280 + kb);
                ldx4(ql, base + B_LO + boff4 + jp * 1280 + kb);
                #pragma unroll
                for (int t = 0; t < 2; t++) {
                    mma_bf16(C[t][2 * jp],     ah[t], qh);
                    mma_bf16(C[t][2 * jp + 1], ah[t], qh + 2);
                    mma_bf16(C[t][2 * jp],     ah[t], ql);
                    mma_bf16(C[t][2 * jp + 1], ah[t], ql + 2);
                    mma_bf16(C[t][2 * jp],     al[t], qh);
                    mma_bf16(C[t][2 * jp + 1], al[t], qh + 2);
                }
            }
            {
                uint32_t q2h[2], q2l[2];
                ldx2(q2h, base + B_HI + boff2 + kb);
                ldx2(q2l, base + B_LO + boff2 + kb);
                #pragma unroll
                for (int t = 0; t < 2; t++) {
                    mma_bf16(C[t][8], ah[t], q2h);
                    mma_bf16(C[t][8], ah[t], q2l);
                    mma_bf16(C[t][8], al[t], q2h);
                }
            }
        }
        __syncthreads();
        if (c + 2 < NCHUNK) issue_loads(sb, s, c + 2, r0, tid);
    }

    // ---- fused epilogue ----
    __syncthreads();   // all warps done reading stage buffers
    float* Cs = (float*)smem;                       // [128][145]
    float* part = (float*)(smem + OFF_PART);        // [140]
    int*   hist = (int*)(smem + OFF_HIST);          // [14]
    if (tid < KM) part[tid] = 0.f;
    if (tid < KCLS) hist[tid] = 0;

    #pragma unroll
    for (int t = 0; t < 2; t++) {
        int rl = warp_m * 32 + t * 16 + (lane >> 2);
        #pragma unroll
        for (int j = 0; j < 9; j++) {
            int cb = warp_n * 72 + j * 8 + 2 * (lane & 3);
            Cs[rl * CSTRIDE_EPI + cb]           = C[t][j][0];
            Cs[rl * CSTRIDE_EPI + cb + 1]       = C[t][j][1];
            Cs[(rl + 8) * CSTRIDE_EPI + cb]     = C[t][j][2];
            Cs[(rl + 8) * CSTRIDE_EPI + cb + 1] = C[t][j][3];
            if (cb < KM) {
                *(float2*)(o_log + (size_t)(r0 + rl) * KM + cb) = make_float2(C[t][j][0], C[t][j][1]);
                *(float2*)(o_log + (size_t)(r0 + rl + 8) * KM + cb) = make_float2(C[t][j][2], C[t][j][3]);
            }
        }
    }
    __syncthreads();

    if (tid < 128) {
        int n = r0 + tid;
        const float* row = Cs + tid * CSTRIDE_EPI;
        float mx[KCLS]; float mean = 0.f;
        #pragma unroll
        for (int k = 0; k < KCLS; k++) {
            float m0 = row[k * MPRO];
            #pragma unroll
            for (int m = 1; m < MPRO; m++) m0 = fmaxf(m0, row[k * MPRO + m]);
            mx[k] = m0; mean += m0;
        }
        mean /= (float)KCLS;
        float var = 0.f;
        #pragma unroll
        for (int k = 0; k < KCLS; k++) { float d = mx[k] - mean; var += d * d; }
        var /= (float)KCLS;
        float inv = 1.f / sqrtf(var + 1e-5f);
        float best = -1e30f; int pred = 0;
        #pragma unroll
        for (int k = 0; k < KCLS; k++) {
            float v = (mx[k] - mean) * inv * mg[k] + mb[k];
            o_seg[(size_t)n * KCLS + k] = v;
            if (v > best) { best = v; pred = k; }
        }
        int gt = gts[n];
        g_corr[n] = (unsigned char)(pred == gt);
        #pragma unroll
        for (int m = 0; m < MPRO; m++) {
            float e = expf(row[gt * MPRO + m] / 0.05f);
            g_e[(size_t)n * MPRO + m] = e;
            atomicAdd(&part[gt * MPRO + m], e);
        }
        atomicAdd(&hist[gt], 1);
    }
    __syncthreads();
    if (tid < KM) atomicAdd(&g_colsum[tid], part[tid]);
    if (tid < KCLS) atomicAdd(&g_Bcnt[tid], hist[tid]);
}

// ---------------- K3: fused sinkhorn row+col pass ----------------
// computes row scale from colsum[pass], accumulates colsum[pass+1]
__global__ void k_rowcol(const int* __restrict__ gts, int pass) {
    __shared__ float part[KM];
    int t = threadIdx.x;
    if (t < KM) part[t] = 0.f;
    __syncthreads();
    int n = blockIdx.x * 256 + t;
    int k = gts[n];
    float e[MPRO];
    float rs = 0.f;
    #pragma unroll
    for (int m = 0; m < MPRO; m++) {
        e[m] = g_e[(size_t)n * MPRO + m];
        float cs = g_colsum[pass * KM + k * MPRO + m];
        rs += e[m] / ((float)MPRO * fmaxf(cs, 1e-30f));
    }
    float B = (float)g_Bcnt[k];
    float r = 1.f / (fmaxf(B, 1.f) * fmaxf(rs, 1e-30f));
    #pragma unroll
    for (int m = 0; m < MPRO; m++)
        atomicAdd(&part[k * MPRO + m], e[m] * r);
    __syncthreads();
    if (t < KM) atomicAdd(&g_colsum[(pass + 1) * KM + t], part[t]);
}

// ---------------- K4: argmax -> target, scatter f ----------------
__global__ void k_final(const int* __restrict__ gts, float* __restrict__ o_tgt) {
    int n = blockIdx.x * 256 + threadIdx.x;
    int lane = threadIdx.x & 31;
    int k = gts[n];
    float best = -1e30f; int idx = 0;
    #pragma unroll
    for (int m = 0; m < MPRO; m++) {
        float cs = g_colsum[2 * KM + k * MPRO + m];
        float val = g_e[(size_t)n * MPRO + m] / fmaxf(cs, 1e-30f);
        if (val > best) { best = val; idx = m; }
    }
    o_tgt[n] = (float)(k * MPRO + idx);
    int bucket = k * MPRO + idx;
    int corr = (int)g_corr[n];
    unsigned mask = __ballot_sync(0xffffffffu, corr != 0);
    while (mask) {
        int src = __ffs(mask) - 1;
        mask &= mask - 1;
        int bn = __shfl_sync(0xffffffffu, n, src);
        int bb = __shfl_sync(0xffffffffu, bucket, src);
        const __nv_bfloat16* ch = g_chi + (size_t)bn * CSTRIDE;
        const __nv_bfloat16* cl = g_clo + (size_t)bn * CSTRIDE;
        for (int c = lane; c < CDIM; c += 32)
            atomicAdd(&g_f[bb * CDIM + c],
                      __bfloat162float(ch[c]) + __bfloat162float(cl[c]));
        if (lane == src) atomicAdd(&g_ncnt[bb], 1);
    }
}

// ---------------- K5: prototype momentum update + final l2norm --------------
__global__ void k_update(float* __restrict__ o_np) {
    __shared__ float s4[4];
    int row = blockIdx.x, t = threadIdx.x;
    float v[4]; float ss = 0.f;
    #pragma unroll
    for (int i = 0; i < 4; i++) {
        int c = t + 128 * i;
        float x = (c < CDIM) ? g_f[row * CDIM + c] : 0.f;
        v[i] = x; ss += x * x;
    }
    ss = blockSum128(ss, s4);
    float inv = 1.f / fmaxf(sqrtf(ss), 1e-12f);
    int cnt = g_ncnt[row];
    float ss2 = 0.f;
    #pragma unroll
    for (int i = 0; i < 4; i++) {
        int c = t + 128 * i;
        if (c < CDIM) {
            float p = g_protos[row * CDIM + c];
            float u = (cnt > 0) ? (0.999f * p + 0.001f * (v[i] * inv)) : p;
            v[i] = u; ss2 += u * u;
        } else v[i] = 0.f;
    }
    ss2 = blockSum128(ss2, s4);
    float inv2 = 1.f / fmaxf(sqrtf(ss2), 1e-12f);
    #pragma unroll
    for (int i = 0; i < 4; i++) {
        int c = t + 128 * i;
        if (c < CDIM) o_np[row * CDIM + c] = v[i] * inv2;
    }
}

// ---------------- launch ----------------
extern "C" void kernel_launch(void* const* d_in, const int* in_sizes, int n_in,
                              void* d_out, int out_size) {
    const float* feat = (const float*)d_in[0];
    const float* protos = (const float*)d_in[1];
    const float* fg = (const float*)d_in[2];
    const float* fb = (const float*)d_in[3];
    const float* mg = (const float*)d_in[4];
    const float* mb = (const float*)d_in[5];
    const int* gts = (const int*)d_in[6];

    float* out = (float*)d_out;
    float* o_seg = out;                                     // [N, 14]
    float* o_log = out + (size_t)NPIX * KCLS;               // [N, 140]
    float* o_tgt = out + (size_t)NPIX * (KCLS + KM);        // [N]
    float* o_np  = out + (size_t)NPIX * (KCLS + KM + 1);    // [140, 434]

    cudaFuncSetAttribute(k_gemm_mma, cudaFuncAttributeMaxDynamicSharedMemorySize, GEMM_SMEM);

    k_zero<<<256, 256>>>();
    k_pnorm<<<KM, 128>>>(protos);
    k_ln<<<NPIX / 8, 256>>>(feat, fg, fb);
    k_gemm_mma<<<NPIX / 128, 256, GEMM_SMEM>>>(o_log, gts, mg, mb, o_seg);
    k_rowcol<<<NPIX / 256, 256>>>(gts, 0);
    k_rowcol<<<NPIX / 256, 256>>>(gts, 1);
    k_final<<<NPIX / 256, 256>>>(gts, o_tgt);
    k_update<<<KM, 128>>>(o_np);
}